// round 16
// baseline (speedup 1.0000x reference)
#include <cuda_runtime.h>
#include <cuda_fp16.h>
#include <cstdint>

// Problem constants (fixed by the reference: B=4, C=256, H=W=48, heads=8)
#define BB    4
#define CC    256
#define HWN   2304
#define HEADS 8
#define DH    32
#define NT    18                             // 128-token tiles
#define SCALE 0.17677669529663687f           // 32^-0.5
#define LOG2E 1.4426950408889634f
#define QSCL  (SCALE * LOG2E)
#define CBIAS 16.0f

// ---------------- scratch (no cudaMalloc allowed) ---------------------------
__device__ uint32_t g_xpk[(size_t)BB * NT * 8 * 2048];       // x packed hi only
__device__ uint32_t g_wqkvpk[6 * 8 * 2048];                  // w_qkv packed (row-permuted)
__device__ uint32_t g_wprojpk[2 * 8 * 2048];                 // w_proj packed
__device__ uint32_t g_qpk[(size_t)BB * HEADS * NT * 2048];   // Q A-frag packed
__device__ uint32_t g_kpk[(size_t)BB * HEADS * 36 * 1024];   // K B-frag packed
__device__ uint32_t g_vpk[(size_t)BB * HEADS * 36 * 1024];   // V B-frag packed
__device__ uint32_t g_apk[(size_t)BB * NT * 8 * 2048];       // attn out packed hi

// ---------------- helpers ---------------------------------------------------
__device__ __forceinline__ float ex2f(float x) {
    float r; asm("ex2.approx.f32 %0, %1;" : "=f"(r) : "f"(x)); return r;
}
__device__ __forceinline__ uint32_t h2pack(float a, float b) {   // a->lo, b->hi
    uint32_t r; asm("cvt.rn.f16x2.f32 %0, %1, %2;" : "=r"(r) : "f"(b), "f"(a)); return r;
}
__device__ __forceinline__ uint32_t smem_u32(const void* p) {
    uint32_t a;
    asm("{ .reg .u64 t; cvta.to.shared.u64 t, %1; cvt.u32.u64 %0, t; }" : "=r"(a) : "l"(p));
    return a;
}
__device__ __forceinline__ void cpa16(uint32_t s, const void* g) {
    asm volatile("cp.async.cg.shared.global [%0], [%1], 16;" :: "r"(s), "l"(g));
}
#define CP_COMMIT() asm volatile("cp.async.commit_group;" ::: "memory")
#define CP_WAIT1()  asm volatile("cp.async.wait_group 1;" ::: "memory")
#define CP_WAIT0()  asm volatile("cp.async.wait_group 0;" ::: "memory")

// fp16 m16n8k16, f32 accumulator
#define MMAH(d, a, b0, b1)                                                        \
    asm volatile("mma.sync.aligned.m16n8k16.row.col.f32.f16.f16.f32 "             \
                 "{%0,%1,%2,%3},{%4,%5,%6,%7},{%8,%9},{%0,%1,%2,%3};"             \
                 : "+f"((d)[0]), "+f"((d)[1]), "+f"((d)[2]), "+f"((d)[3])         \
                 : "r"((a)[0]), "r"((a)[1]), "r"((a)[2]), "r"((a)[3]),            \
                   "r"(b0), "r"(b1))

// packed fp16x2 FMA on the fma pipe (scalar offload path)
#define HFMA2A(acc, a, b) \
    asm("fma.rn.f16x2 %0, %1, %2, %0;" : "+r"(acc) : "r"(a), "r"(b))

// ---------------------------------------------------------------------------
// pack_all: one launch packs w_qkv (blocks [0,384), perm), w_proj ([384,512)),
// and x ([512,1088)).
// ---------------------------------------------------------------------------
__global__ void pack_all(const float* __restrict__ Wq,
                         const float* __restrict__ Wp,
                         const float* __restrict__ X,
                         uint32_t* __restrict__ wqo,
                         uint32_t* __restrict__ wpo,
                         uint32_t* __restrict__ xo)
{
    int blk = blockIdx.x;
    int tid = threadIdx.x;
    if (blk < 512) {
        const float* W = (blk < 384) ? Wq : Wp;
        uint32_t* out  = (blk < 384) ? wqo : wpo;
        int perm       = (blk < 384) ? 1 : 0;
        int gid = (blk < 384 ? blk : blk - 384) * 256 + tid;
        int k2  = gid & 15;
        int row = (gid >> 4) & 127;
        int ch  = (gid >> 11) & 7;
        int mt  = gid >> 14;
        int r = row & 15;
        int rphys = perm ? ((r < 8) ? 2 * r : 2 * r - 15) : r;
        int wrow = mt * 128 + (row & ~15) + rphys;
        float2 v = *(const float2*)&W[(size_t)wrow * CC + ch * 32 + 2 * k2];
        int mf = row >> 4;
        int gq2 = r & 7, half = r >> 3;
        int kf = k2 >> 3, k2l = k2 & 7;
        int reg = half + 2 * (k2l >> 2);
        int ln  = gq2 * 4 + (k2l & 3);
        out[(size_t)(mt * 8 + ch) * 2048 + ((mf * 2 + kf) * 32 + ln) * 4 + reg] =
            h2pack(v.x, v.y);
    } else {
        int idx = blk - 512;                  // [0, 576)
        int b  = idx / (NT * 8);
        int r8 = idx % (NT * 8);
        int nt = r8 >> 3, ch = r8 & 7;
        const float* xb = X + ((size_t)b * CC + ch * 32) * HWN + nt * 128;
        uint32_t* o = xo + (size_t)((b * NT + nt) * 8 + ch) * 2048;
#pragma unroll
        for (int it = 0; it < 8; it++) {
            int p = it * 256 + tid;
            int n = p & 127, k2 = p >> 7;
            float v0 = xb[(size_t)(2 * k2) * HWN + n];
            float v1 = xb[(size_t)(2 * k2 + 1) * HWN + n];
            int nf = n >> 3, gq2 = n & 7;
            int kf = k2 >> 3, k2l = k2 & 7;
            int reg = k2l >> 2;
            int ln  = gq2 * 4 + (k2l & 3);
            o[((kf * 16 + nf) * 32 + ln) * 2 + reg] = h2pack(v0, v1);
        }
    }
}

// ---------------------------------------------------------------------------
// QKV GEMM, fp16 1-term, 128x128 tiles, 3-stage cp.async (R15, unchanged).
// ---------------------------------------------------------------------------
__global__ void __launch_bounds__(256, 2)
gemm_qkv(const uint32_t* __restrict__ Apk, const uint32_t* __restrict__ Bpk,
         const float* __restrict__ bias,
         uint32_t* __restrict__ qpk, uint32_t* __restrict__ kpk,
         uint32_t* __restrict__ vpk)
{
    __shared__ uint32_t sm[3 * 4096];

    const int tid  = threadIdx.x;
    const int lane = tid & 31;
    const int w    = tid >> 5;
    const int wm   = w >> 2;
    const int wn   = w & 3;
    const int cq   = lane & 3;
    const int gq   = lane >> 2;

    const int nt = blockIdx.x, mt = blockIdx.y, b = blockIdx.z;
    const uint32_t smb = smem_u32(sm);
    const uint32_t* Ab = Apk + (size_t)mt * (8 * 2048);
    const uint32_t* Bb = Bpk + (size_t)((b * NT + nt) * 8) * 2048;

    float acc[4][4][4];
#pragma unroll
    for (int i = 0; i < 4; i++)
#pragma unroll
        for (int j = 0; j < 4; j++)
#pragma unroll
            for (int r = 0; r < 4; r++) acc[i][j][r] = 0.f;

#define Q_ISSUE(c, buf) do {                                                      \
        uint32_t d_ = smb + (buf) * 16384;                                        \
        const uint32_t* A_ = Ab + (c) * 2048;                                     \
        const uint32_t* B_ = Bb + (c) * 2048;                                     \
        cpa16(d_ + tid * 32,             A_ + tid * 8);                           \
        cpa16(d_ + tid * 32 + 16,        A_ + tid * 8 + 4);                       \
        cpa16(d_ + 8192 + tid * 32,      B_ + tid * 8);                           \
        cpa16(d_ + 8192 + tid * 32 + 16, B_ + tid * 8 + 4);                       \
    } while (0)

    Q_ISSUE(0, 0); CP_COMMIT();
    Q_ISSUE(1, 1); CP_COMMIT();

#pragma unroll
    for (int c = 0; c < 8; c++) {
        if (c < 7) { CP_WAIT1(); } else { CP_WAIT0(); }
        __syncthreads();

        const int bo = (c % 3) * 4096;
#pragma unroll
        for (int kf = 0; kf < 2; kf++) {
            uint2 bh[4];
#pragma unroll
            for (int nf = 0; nf < 4; nf++)
                bh[nf] = *(const uint2*)&sm[bo + 2048 +
                            ((kf * 16 + wn * 4 + nf) * 32 + lane) * 2];
#pragma unroll
            for (int mf = 0; mf < 4; mf++) {
                uint4 hh = *(const uint4*)&sm[bo + (((wm * 4 + mf) * 2 + kf) * 32 + lane) * 4];
                uint32_t ah[4] = {hh.x, hh.y, hh.z, hh.w};
#pragma unroll
                for (int nf = 0; nf < 4; nf++)
                    MMAH(acc[mf][nf], ah, bh[nf].x, bh[nf].y);
            }
        }
        if (c < 6) { Q_ISSUE(c + 2, (c + 2) % 3); CP_COMMIT(); }
    }
#undef Q_ISSUE

#pragma unroll
    for (int mf = 0; mf < 4; mf++) {
        int chA = mt * 128 + wm * 64 + mf * 16 + 2 * gq;   // even
        float bA = bias[chA], bB = bias[chA + 1];
#pragma unroll
        for (int nf = 0; nf < 4; nf++) {
            float y0 = acc[mf][nf][0] + bA, y1 = acc[mf][nf][1] + bA;
            float y2 = acc[mf][nf][2] + bB, y3 = acc[mf][nf][3] + bB;
            int qloc = wn * 32 + nf * 8 + 2 * cq;          // even, local token
            if (mt < 2) {
                int h = chA >> 5, dp = (chA & 31) >> 1;
                uint32_t* dst = qpk + ((size_t)((b * 8 + h) * NT + nt)) * 2048
                                    + dp * 128 + qloc;
                *(uint2*)dst = make_uint2(h2pack(y0 * QSCL, y2 * QSCL),
                                          h2pack(y1 * QSCL, y3 * QSCL));
            } else if (mt < 4) {
                int ch = chA - 256;
                int h = ch >> 5, dp = (ch & 31) >> 1;
                int tok = nt * 128 + qloc;
                int t = tok >> 6, key = tok & 63;
                int kg = dp >> 3, reg = (dp >> 2) & 1;
                int u0 = ((kg * 8 + (key >> 3)) * 32 + (key & 7) * 4 + (dp & 3)) * 2 + reg;
                uint32_t* dst = kpk + ((size_t)((b * 8 + h) * 36 + t)) * 1024;
                dst[u0]     = h2pack(y0, y2);
                dst[u0 + 8] = h2pack(y1, y3);
            } else {
                int ch = chA - 512;
                int h = ch >> 5, dA = ch & 31;
                int tok = nt * 128 + qloc;
                int t = tok >> 6, key = tok & 63;
                int kgv = key >> 4, reg = (key >> 3) & 1;
                int uA = ((kgv * 4 + (dA >> 3)) * 32 + (dA & 7) * 4 + ((key >> 1) & 3)) * 2 + reg;
                uint32_t* dst = vpk + ((size_t)((b * 8 + h) * 36 + t)) * 1024;
                dst[uA]     = h2pack(y0, y1);
                dst[uA + 8] = h2pack(y2, y3);
            }
        }
    }
}

// ---------------------------------------------------------------------------
// Proj GEMM, fp16 1-term, 128x128 tiles, 3-stage pipeline (R15, unchanged).
// ---------------------------------------------------------------------------
__global__ void __launch_bounds__(256, 2)
gemm_proj(const uint32_t* __restrict__ Apk, const uint32_t* __restrict__ Bpk,
          const float* __restrict__ bias, float* __restrict__ Y)
{
    __shared__ uint32_t sm[3 * 4096];

    const int tid  = threadIdx.x;
    const int lane = tid & 31;
    const int w    = tid >> 5;
    const int wm   = w >> 2;
    const int wn   = w & 3;
    const int cq   = lane & 3;
    const int gq   = lane >> 2;

    const uint32_t smb = smem_u32(sm);
    const uint32_t* Ab = Apk + (size_t)blockIdx.y * (8 * 2048);
    const uint32_t* Bb = Bpk + (size_t)((blockIdx.z * NT + blockIdx.x) * 8) * 2048;

    float acc[4][4][4];
#pragma unroll
    for (int i = 0; i < 4; i++)
#pragma unroll
        for (int j = 0; j < 4; j++)
#pragma unroll
            for (int r = 0; r < 4; r++) acc[i][j][r] = 0.f;

#define P_ISSUE(c, buf) do {                                                      \
        uint32_t d_ = smb + (buf) * 16384;                                        \
        const uint32_t* A_ = Ab + (c) * 2048;                                     \
        const uint32_t* B_ = Bb + (c) * 2048;                                     \
        cpa16(d_ + tid * 32,             A_ + tid * 8);                           \
        cpa16(d_ + tid * 32 + 16,        A_ + tid * 8 + 4);                       \
        cpa16(d_ + 8192 + tid * 32,      B_ + tid * 8);                           \
        cpa16(d_ + 8192 + tid * 32 + 16, B_ + tid * 8 + 4);                       \
    } while (0)

    P_ISSUE(0, 0); CP_COMMIT();
    P_ISSUE(1, 1); CP_COMMIT();

#pragma unroll
    for (int c = 0; c < 8; c++) {
        if (c < 7) { CP_WAIT1(); } else { CP_WAIT0(); }
        __syncthreads();

        const int bo = (c % 3) * 4096;
#pragma unroll
        for (int kf = 0; kf < 2; kf++) {
            uint2 bh[4];
#pragma unroll
            for (int nf = 0; nf < 4; nf++)
                bh[nf] = *(const uint2*)&sm[bo + 2048 +
                            ((kf * 16 + wn * 4 + nf) * 32 + lane) * 2];
#pragma unroll
            for (int mf = 0; mf < 4; mf++) {
                uint4 hh = *(const uint4*)&sm[bo + (((wm * 4 + mf) * 2 + kf) * 32 + lane) * 4];
                uint32_t ah[4] = {hh.x, hh.y, hh.z, hh.w};
#pragma unroll
                for (int nf = 0; nf < 4; nf++)
                    MMAH(acc[mf][nf], ah, bh[nf].x, bh[nf].y);
            }
        }
        if (c < 6) { P_ISSUE(c + 2, (c + 2) % 3); CP_COMMIT(); }
    }
#undef P_ISSUE

    float* Yb = Y + (size_t)blockIdx.z * CC * HWN;
    const int m0 = blockIdx.y * 128;
    const int n0 = blockIdx.x * 128;
#pragma unroll
    for (int mf = 0; mf < 4; mf++) {
        int mA = m0 + wm * 64 + mf * 16 + gq;
        int mB = mA + 8;
        float bvA = bias[mA], bvB = bias[mB];
#pragma unroll
        for (int nf = 0; nf < 4; nf++) {
            int n = n0 + wn * 32 + nf * 8 + 2 * cq;
            *(float2*)&Yb[(size_t)mA * HWN + n] =
                make_float2(acc[mf][nf][0] + bvA, acc[mf][nf][1] + bvA);
            *(float2*)&Yb[(size_t)mB * HWN + n] =
                make_float2(acc[mf][nf][2] + bvB, acc[mf][nf][3] + bvB);
        }
    }
}

// ---------------------------------------------------------------------------
// Flash attention, DUAL-PIPE: tensor path handles keys 0..55 of each tile;
// the fma pipe (HFMA2, one query row per thread) handles keys 56..63.
// Scalar o accumulates fp16-pairwise per 2 tiles, promoted to fp32 in smem.
// smem: 3 x (K 4KB | V 4KB) pipeline + 16KB fp32 oS + 512B rowsum = 41.5KB.
// ---------------------------------------------------------------------------
__global__ void __launch_bounds__(128)
attn_mma_h(const uint32_t* __restrict__ qpk,
           const uint32_t* __restrict__ kpk, const uint32_t* __restrict__ vpk,
           uint32_t* __restrict__ apk)
{
    __shared__ uint32_t smu[3 * 2048 + 4096 + 128];
    float* smOS = (float*)(smu + 6144);        // [d][row] 32x128
    float* smRS = (float*)(smu + 6144 + 4096); // [row]

    const int tid  = threadIdx.x;
    const int lane = tid & 31;
    const int w    = tid >> 5;
    const int cq   = lane & 3;
    const int gq   = lane >> 2;

    const int bh = blockIdx.y;
    const int b  = bh >> 3, h = bh & 7;

    const uint32_t* qp = qpk + ((size_t)(bh * NT + blockIdx.x)) * 2048;
    const uint32_t* kt = kpk + (size_t)(bh * 36) * 1024;
    const uint32_t* vt = vpk + (size_t)(bh * 36) * 1024;
    const uint32_t smb = smem_u32(smu);

    // tensor-path Q frags
    uint32_t qa[2][2][4];
#pragma unroll
    for (int mf = 0; mf < 2; mf++)
#pragma unroll
        for (int kg = 0; kg < 2; kg++) {
            int rA = w * 32 + mf * 16 + gq, rB = rA + 8;
            int dp0 = kg * 8 + cq, dp2 = dp0 + 4;
            qa[mf][kg][0] = qp[dp0 * 128 + rA];
            qa[mf][kg][1] = qp[dp0 * 128 + rB];
            qa[mf][kg][2] = qp[dp2 * 128 + rA];
            qa[mf][kg][3] = qp[dp2 * 128 + rB];
        }
    // scalar-path Q row (thread = row tid), fp16x2 d-pairs, QSCL included
    uint32_t qrow[16];
#pragma unroll
    for (int dp = 0; dp < 16; dp++) qrow[dp] = qp[dp * 128 + tid];

    // zero scalar fp32 accumulator region (per-thread exclusive columns)
#pragma unroll
    for (int d = 0; d < 32; d++) smOS[d * 128 + tid] = 0.f;

    float o[2][4][4];
#pragma unroll
    for (int mf = 0; mf < 2; mf++)
#pragma unroll
        for (int nf = 0; nf < 4; nf++)
#pragma unroll
            for (int i = 0; i < 4; i++) o[mf][nf][i] = 0.f;
    float rs[2][2] = {{0.f, 0.f}, {0.f, 0.f}};
    float rowsumS = 0.f;
    uint32_t o16[32];
#pragma unroll
    for (int d = 0; d < 32; d++) o16[d] = 0u;

#define A_ISSUE(t, buf) do {                                                      \
        uint32_t d_ = smb + (buf) * 8192;                                         \
        const uint32_t* K_ = kt + (t) * 1024;                                     \
        const uint32_t* V_ = vt + (t) * 1024;                                     \
        cpa16(d_ + tid * 32,             K_ + tid * 8);                           \
        cpa16(d_ + tid * 32 + 16,        K_ + tid * 8 + 4);                       \
        cpa16(d_ + 4096 + tid * 32,      V_ + tid * 8);                           \
        cpa16(d_ + 4096 + tid * 32 + 16, V_ + tid * 8 + 4);                       \
    } while (0)

    A_ISSUE(0, 0); CP_COMMIT();
    A_ISSUE(1, 1); CP_COMMIT();

    int buf = 0;
    for (int t = 0; t < 36; t++) {
        if (t < 35) { CP_WAIT1(); } else { CP_WAIT0(); }
        __syncthreads();

        const int bo = buf * 2048;
#pragma unroll
        for (int ch = 0; ch < 2; ch++) {
            float s[2][4][4];
#pragma unroll
            for (int mf = 0; mf < 2; mf++)
#pragma unroll
                for (int nf = 0; nf < 4; nf++)
#pragma unroll
                    for (int i = 0; i < 4; i++) s[mf][nf][i] = -CBIAS;

            // tensor QK (skip keys 56..63 = ch1,nf3 -> scalar-owned)
#pragma unroll
            for (int nf = 0; nf < 4; nf++) {
                if (ch == 1 && nf == 3) continue;
                uint2 kh[2];
#pragma unroll
                for (int kg = 0; kg < 2; kg++)
                    kh[kg] = *(const uint2*)&smu[bo + ((kg * 8 + ch * 4 + nf) * 32 + lane) * 2];
#pragma unroll
                for (int mf = 0; mf < 2; mf++)
#pragma unroll
                    for (int kg = 0; kg < 2; kg++)
                        MMAH(s[mf][nf], qa[mf][kg], kh[kg].x, kh[kg].y);
            }

            // scalar path for keys 56..63 (fma pipe, overlaps HMMA drain)
            if (ch == 1) {
                float p8[8];
#pragma unroll
                for (int jj = 0; jj < 8; jj++) {
                    uint32_t acc = 0;
#pragma unroll
                    for (int kg = 0; kg < 2; kg++) {
                        int base = bo + ((kg * 8 + 7) * 32 + jj * 4) * 2;
                        uint4 ka = *(const uint4*)&smu[base];
                        uint4 kb = *(const uint4*)&smu[base + 4];
                        HFMA2A(acc, qrow[kg * 8 + 0], ka.x);
                        HFMA2A(acc, qrow[kg * 8 + 4], ka.y);
                        HFMA2A(acc, qrow[kg * 8 + 1], ka.z);
                        HFMA2A(acc, qrow[kg * 8 + 5], ka.w);
                        HFMA2A(acc, qrow[kg * 8 + 2], kb.x);
                        HFMA2A(acc, qrow[kg * 8 + 6], kb.y);
                        HFMA2A(acc, qrow[kg * 8 + 3], kb.z);
                        HFMA2A(acc, qrow[kg * 8 + 7], kb.w);
                    }
                    float2 hv = __half22float2(*(__half2*)&acc);
                    float p = ex2f(hv.x + hv.y - CBIAS);
                    rowsumS += p;
                    p8[jj] = p;
                }
#pragma unroll
                for (int pr = 0; pr < 4; pr++) {
                    uint32_t p2 = h2pack(p8[2 * pr], p8[2 * pr + 1]);
#pragma unroll
                    for (int d = 0; d < 32; d++) {
                        uint32_t vv = smu[bo + 1024 +
                            ((12 + (d >> 3)) * 32 + (d & 7) * 4 + pr) * 2 + 1];
                        HFMA2A(o16[d], p2, vv);
                    }
                }
            }

            // softmax (zero scalar-owned octet) + rowsum
#pragma unroll
            for (int mf = 0; mf < 2; mf++)
#pragma unroll
                for (int nf = 0; nf < 4; nf++)
#pragma unroll
                    for (int i = 0; i < 4; i++) {
                        if (ch == 1 && nf == 3) { s[mf][3][i] = 0.f; continue; }
                        float pv = ex2f(s[mf][nf][i]);
                        s[mf][nf][i] = pv;
                        rs[mf][i >> 1] += pv;
                    }

            // tensor PV (p for keys 56..63 is zero -> correct)
#pragma unroll
            for (int kg2 = 0; kg2 < 2; kg2++) {
                uint32_t pa[2][4];
#pragma unroll
                for (int mf = 0; mf < 2; mf++) {
                    pa[mf][0] = h2pack(s[mf][2 * kg2][0],     s[mf][2 * kg2][1]);
                    pa[mf][1] = h2pack(s[mf][2 * kg2][2],     s[mf][2 * kg2][3]);
                    pa[mf][2] = h2pack(s[mf][2 * kg2 + 1][0], s[mf][2 * kg2 + 1][1]);
                    pa[mf][3] = h2pack(s[mf][2 * kg2 + 1][2], s[mf][2 * kg2 + 1][3]);
                }
#pragma unroll
                for (int nf = 0; nf < 4; nf++) {
                    uint2 vv = *(const uint2*)&smu[bo + 1024 +
                                  (((ch * 2 + kg2) * 4 + nf) * 32 + lane) * 2];
#pragma unroll
                    for (int mf = 0; mf < 2; mf++)
                        MMAH(o[mf][nf], pa[mf], vv.x, vv.y);
                }
            }
        }

        // promote scalar fp16 partials to fp32 every 2 tiles
        if (t & 1) {
#pragma unroll
            for (int d = 0; d < 32; d++) {
                float2 f = __half22float2(*(__half2*)&o16[d]);
                smOS[d * 128 + tid] += f.x + f.y;
                o16[d] = 0u;
            }
        }

        if (t < 34) { A_ISSUE(t + 2, (buf + 2 >= 3) ? buf - 1 : buf + 2); CP_COMMIT(); }
        buf = (buf + 1 == 3) ? 0 : buf + 1;
    }
#undef A_ISSUE

    smRS[tid] = rowsumS;
    __syncthreads();

    // rowsum: quad-reduce tensor part, add scalar part, invert
#pragma unroll
    for (int mf = 0; mf < 2; mf++)
#pragma unroll
        for (int hf = 0; hf < 2; hf++) {
            float v = rs[mf][hf];
            v += __shfl_xor_sync(0xffffffffu, v, 1);
            v += __shfl_xor_sync(0xffffffffu, v, 2);
            int row = w * 32 + mf * 16 + gq + 8 * hf;
            v += smRS[row];
            rs[mf][hf] = 1.f / fmaxf(v, 1e-12f);
        }

    // epilogue: merge scalar o, write proj's packed B (hi only)
    uint32_t* op = apk + (size_t)((b * NT + blockIdx.x) * 8 + h) * 2048;
#pragma unroll
    for (int mf = 0; mf < 2; mf++)
#pragma unroll
        for (int nfo = 0; nfo < 4; nfo++)
#pragma unroll
            for (int ih = 0; ih < 2; ih++) {
                float rv = rs[mf][ih];
                int row = w * 32 + mf * 16 + gq + 8 * ih;
                int d0  = nfo * 8 + 2 * cq;
                float f0 = (o[mf][nfo][2 * ih + 0] + smOS[d0 * 128 + row]) * rv;
                float f1 = (o[mf][nfo][2 * ih + 1] + smOS[(d0 + 1) * 128 + row]) * rv;
                int k2  = nfo * 4 + cq;
                int kf  = k2 >> 3;
                int reg = (k2 & 7) >> 2;
                int nf  = w * 4 + mf * 2 + ih;
                op[((kf * 16 + nf) * 32 + lane) * 2 + reg] = h2pack(f0, f1);
            }
}

// ---------------------------------------------------------------------------
extern "C" void kernel_launch(void* const* d_in, const int* in_sizes, int n_in,
                              void* d_out, int out_size)
{
    const float* x      = (const float*)d_in[0];
    const float* w_qkv  = (const float*)d_in[1];
    const float* b_qkv  = (const float*)d_in[2];
    const float* w_proj = (const float*)d_in[3];
    const float* b_proj = (const float*)d_in[4];
    float*       out    = (float*)d_out;

    void *p_xpk, *p_wq, *p_wp, *p_qpk, *p_kpk, *p_vpk, *p_apk;
    cudaGetSymbolAddress(&p_xpk, g_xpk);
    cudaGetSymbolAddress(&p_wq,  g_wqkvpk);
    cudaGetSymbolAddress(&p_wp,  g_wprojpk);
    cudaGetSymbolAddress(&p_qpk, g_qpk);
    cudaGetSymbolAddress(&p_kpk, g_kpk);
    cudaGetSymbolAddress(&p_vpk, g_vpk);
    cudaGetSymbolAddress(&p_apk, g_apk);

    // 0) pack everything in one launch
    pack_all<<<1088, 256>>>(w_qkv, w_proj, x,
                            (uint32_t*)p_wq, (uint32_t*)p_wp, (uint32_t*)p_xpk);

    // 1) QKV projection (fp16 1-term, 3-stage pipeline) + fused Q/K/V packing
    {
        dim3 grid(NT, 6, BB);
        gemm_qkv<<<grid, 256>>>((const uint32_t*)p_wq, (const uint32_t*)p_xpk,
                                b_qkv, (uint32_t*)p_qpk, (uint32_t*)p_kpk,
                                (uint32_t*)p_vpk);
    }

    // 2) attention (dual-pipe: tensor + fma offload)
    {
        dim3 grid(NT, BB * HEADS);
        attn_mma_h<<<grid, 128>>>((const uint32_t*)p_qpk, (const uint32_t*)p_kpk,
                                  (const uint32_t*)p_vpk, (uint32_t*)p_apk);
    }

    // 3) output projection (fp16 1-term, 3-stage pipeline)
    {
        dim3 grid(NT, 2, BB);
        gemm_proj<<<grid, 256>>>((const uint32_t*)p_wp, (const uint32_t*)p_apk,
                                 b_proj, out);
    }
}

// round 17
// speedup vs baseline: 2.3095x; 2.3095x over previous
#include <cuda_runtime.h>
#include <cuda_fp16.h>
#include <cstdint>

// Problem constants (fixed by the reference: B=4, C=256, H=W=48, heads=8)
#define BB    4
#define CC    256
#define HWN   2304
#define HEADS 8
#define DH    32
#define NT    18                             // 128-token tiles
#define SCALE 0.17677669529663687f           // 32^-0.5
#define LOG2E 1.4426950408889634f
#define QSCL  (SCALE * LOG2E)
#define CBIAS 16.0f

// ---------------- scratch (no cudaMalloc allowed) ---------------------------
__device__ uint32_t g_xpk[(size_t)BB * NT * 8 * 2048];       // x packed hi only
__device__ uint32_t g_wqkvpk[6 * 8 * 2048];                  // w_qkv packed (row-permuted)
__device__ uint32_t g_wprojpk[2 * 8 * 2048];                 // w_proj packed
__device__ uint32_t g_qpk[(size_t)BB * HEADS * NT * 2048];   // Q A-frag packed
__device__ uint32_t g_kpk[(size_t)BB * HEADS * 36 * 1024];   // K B-frag packed
__device__ uint32_t g_vpk[(size_t)BB * HEADS * 36 * 1024];   // V B-frag packed
__device__ uint32_t g_apk[(size_t)BB * NT * 8 * 2048];       // attn out packed hi

// ---------------- helpers ---------------------------------------------------
__device__ __forceinline__ float ex2f(float x) {
    float r; asm("ex2.approx.f32 %0, %1;" : "=f"(r) : "f"(x)); return r;
}
__device__ __forceinline__ uint32_t h2pack(float a, float b) {   // a->lo, b->hi
    uint32_t r; asm("cvt.rn.f16x2.f32 %0, %1, %2;" : "=r"(r) : "f"(b), "f"(a)); return r;
}
__device__ __forceinline__ uint32_t smem_u32(const void* p) {
    uint32_t a;
    asm("{ .reg .u64 t; cvta.to.shared.u64 t, %1; cvt.u32.u64 %0, t; }" : "=r"(a) : "l"(p));
    return a;
}
__device__ __forceinline__ void cpa16(uint32_t s, const void* g) {
    asm volatile("cp.async.cg.shared.global [%0], [%1], 16;" :: "r"(s), "l"(g));
}
#define CP_COMMIT() asm volatile("cp.async.commit_group;" ::: "memory")
#define CP_WAIT1()  asm volatile("cp.async.wait_group 1;" ::: "memory")
#define CP_WAIT0()  asm volatile("cp.async.wait_group 0;" ::: "memory")

// fp16 m16n8k16, f32 accumulator
#define MMAH(d, a, b0, b1)                                                        \
    asm volatile("mma.sync.aligned.m16n8k16.row.col.f32.f16.f16.f32 "             \
                 "{%0,%1,%2,%3},{%4,%5,%6,%7},{%8,%9},{%0,%1,%2,%3};"             \
                 : "+f"((d)[0]), "+f"((d)[1]), "+f"((d)[2]), "+f"((d)[3])         \
                 : "r"((a)[0]), "r"((a)[1]), "r"((a)[2]), "r"((a)[3]),            \
                   "r"(b0), "r"(b1))

// ---------------------------------------------------------------------------
// pack_all: one launch packs w_qkv (blocks [0,384), perm), w_proj ([384,512)),
// and x ([512,1088)).
// ---------------------------------------------------------------------------
__global__ void pack_all(const float* __restrict__ Wq,
                         const float* __restrict__ Wp,
                         const float* __restrict__ X,
                         uint32_t* __restrict__ wqo,
                         uint32_t* __restrict__ wpo,
                         uint32_t* __restrict__ xo)
{
    int blk = blockIdx.x;
    int tid = threadIdx.x;
    if (blk < 512) {
        const float* W = (blk < 384) ? Wq : Wp;
        uint32_t* out  = (blk < 384) ? wqo : wpo;
        int perm       = (blk < 384) ? 1 : 0;
        int gid = (blk < 384 ? blk : blk - 384) * 256 + tid;
        int k2  = gid & 15;
        int row = (gid >> 4) & 127;
        int ch  = (gid >> 11) & 7;
        int mt  = gid >> 14;
        int r = row & 15;
        int rphys = perm ? ((r < 8) ? 2 * r : 2 * r - 15) : r;
        int wrow = mt * 128 + (row & ~15) + rphys;
        float2 v = *(const float2*)&W[(size_t)wrow * CC + ch * 32 + 2 * k2];
        int mf = row >> 4;
        int gq2 = r & 7, half = r >> 3;
        int kf = k2 >> 3, k2l = k2 & 7;
        int reg = half + 2 * (k2l >> 2);
        int ln  = gq2 * 4 + (k2l & 3);
        out[(size_t)(mt * 8 + ch) * 2048 + ((mf * 2 + kf) * 32 + ln) * 4 + reg] =
            h2pack(v.x, v.y);
    } else {
        int idx = blk - 512;                  // [0, 576)
        int b  = idx / (NT * 8);
        int r8 = idx % (NT * 8);
        int nt = r8 >> 3, ch = r8 & 7;
        const float* xb = X + ((size_t)b * CC + ch * 32) * HWN + nt * 128;
        uint32_t* o = xo + (size_t)((b * NT + nt) * 8 + ch) * 2048;
#pragma unroll
        for (int it = 0; it < 8; it++) {
            int p = it * 256 + tid;
            int n = p & 127, k2 = p >> 7;
            float v0 = xb[(size_t)(2 * k2) * HWN + n];
            float v1 = xb[(size_t)(2 * k2 + 1) * HWN + n];
            int nf = n >> 3, gq2 = n & 7;
            int kf = k2 >> 3, k2l = k2 & 7;
            int reg = k2l >> 2;
            int ln  = gq2 * 4 + (k2l & 3);
            o[((kf * 16 + nf) * 32 + ln) * 2 + reg] = h2pack(v0, v1);
        }
    }
}

// ---------------------------------------------------------------------------
// QKV GEMM, fp16 1-term, 128x128 tiles, 3-stage cp.async, ONE sync per chunk.
// grid (NT, 6, BB). Epilogue writes Q/K/V in attention fragment layouts.
// smem: 3 stages x (A 2048 | B 2048) u32 = 48KB.
// ---------------------------------------------------------------------------
__global__ void __launch_bounds__(256, 2)
gemm_qkv(const uint32_t* __restrict__ Apk, const uint32_t* __restrict__ Bpk,
         const float* __restrict__ bias,
         uint32_t* __restrict__ qpk, uint32_t* __restrict__ kpk,
         uint32_t* __restrict__ vpk)
{
    __shared__ uint32_t sm[3 * 4096];

    const int tid  = threadIdx.x;
    const int lane = tid & 31;
    const int w    = tid >> 5;
    const int wm   = w >> 2;
    const int wn   = w & 3;
    const int cq   = lane & 3;
    const int gq   = lane >> 2;

    const int nt = blockIdx.x, mt = blockIdx.y, b = blockIdx.z;
    const uint32_t smb = smem_u32(sm);
    const uint32_t* Ab = Apk + (size_t)mt * (8 * 2048);
    const uint32_t* Bb = Bpk + (size_t)((b * NT + nt) * 8) * 2048;

    float acc[4][4][4];
#pragma unroll
    for (int i = 0; i < 4; i++)
#pragma unroll
        for (int j = 0; j < 4; j++)
#pragma unroll
            for (int r = 0; r < 4; r++) acc[i][j][r] = 0.f;

#define Q_ISSUE(c, buf) do {                                                      \
        uint32_t d_ = smb + (buf) * 16384;                                        \
        const uint32_t* A_ = Ab + (c) * 2048;                                     \
        const uint32_t* B_ = Bb + (c) * 2048;                                     \
        cpa16(d_ + tid * 32,             A_ + tid * 8);                           \
        cpa16(d_ + tid * 32 + 16,        A_ + tid * 8 + 4);                       \
        cpa16(d_ + 8192 + tid * 32,      B_ + tid * 8);                           \
        cpa16(d_ + 8192 + tid * 32 + 16, B_ + tid * 8 + 4);                       \
    } while (0)

    Q_ISSUE(0, 0); CP_COMMIT();
    Q_ISSUE(1, 1); CP_COMMIT();

#pragma unroll
    for (int c = 0; c < 8; c++) {
        if (c < 7) { CP_WAIT1(); } else { CP_WAIT0(); }
        __syncthreads();

        const int bo = (c % 3) * 4096;
#pragma unroll
        for (int kf = 0; kf < 2; kf++) {
            uint2 bh[4];
#pragma unroll
            for (int nf = 0; nf < 4; nf++)
                bh[nf] = *(const uint2*)&sm[bo + 2048 +
                            ((kf * 16 + wn * 4 + nf) * 32 + lane) * 2];
#pragma unroll
            for (int mf = 0; mf < 4; mf++) {
                uint4 hh = *(const uint4*)&sm[bo + (((wm * 4 + mf) * 2 + kf) * 32 + lane) * 4];
                uint32_t ah[4] = {hh.x, hh.y, hh.z, hh.w};
#pragma unroll
                for (int nf = 0; nf < 4; nf++)
                    MMAH(acc[mf][nf], ah, bh[nf].x, bh[nf].y);
            }
        }
        if (c < 6) { Q_ISSUE(c + 2, (c + 2) % 3); CP_COMMIT(); }
    }
#undef Q_ISSUE

    // epilogue: rows (mA,mB) hold adjacent channels via W permutation
#pragma unroll
    for (int mf = 0; mf < 4; mf++) {
        int chA = mt * 128 + wm * 64 + mf * 16 + 2 * gq;   // even
        float bA = bias[chA], bB = bias[chA + 1];
#pragma unroll
        for (int nf = 0; nf < 4; nf++) {
            float y0 = acc[mf][nf][0] + bA, y1 = acc[mf][nf][1] + bA;
            float y2 = acc[mf][nf][2] + bB, y3 = acc[mf][nf][3] + bB;
            int qloc = wn * 32 + nf * 8 + 2 * cq;          // even, local token
            if (mt < 2) {
                int h = chA >> 5, dp = (chA & 31) >> 1;
                uint32_t* dst = qpk + ((size_t)((b * 8 + h) * NT + nt)) * 2048
                                    + dp * 128 + qloc;
                *(uint2*)dst = make_uint2(h2pack(y0 * QSCL, y2 * QSCL),
                                          h2pack(y1 * QSCL, y3 * QSCL));
            } else if (mt < 4) {
                int ch = chA - 256;
                int h = ch >> 5, dp = (ch & 31) >> 1;
                int tok = nt * 128 + qloc;
                int t = tok >> 6, key = tok & 63;
                int kg = dp >> 3, reg = (dp >> 2) & 1;
                int u0 = ((kg * 8 + (key >> 3)) * 32 + (key & 7) * 4 + (dp & 3)) * 2 + reg;
                uint32_t* dst = kpk + ((size_t)((b * 8 + h) * 36 + t)) * 1024;
                dst[u0]     = h2pack(y0, y2);
                dst[u0 + 8] = h2pack(y1, y3);
            } else {
                int ch = chA - 512;
                int h = ch >> 5, dA = ch & 31;
                int tok = nt * 128 + qloc;
                int t = tok >> 6, key = tok & 63;
                int kgv = key >> 4, reg = (key >> 3) & 1;
                int uA = ((kgv * 4 + (dA >> 3)) * 32 + (dA & 7) * 4 + ((key >> 1) & 3)) * 2 + reg;
                uint32_t* dst = vpk + ((size_t)((b * 8 + h) * 36 + t)) * 1024;
                dst[uA]     = h2pack(y0, y1);
                dst[uA + 8] = h2pack(y2, y3);
            }
        }
    }
}

// ---------------------------------------------------------------------------
// Proj GEMM, fp16 1-term, 128x128 tiles, 3-stage pipeline. grid (NT, 2, BB).
// ---------------------------------------------------------------------------
__global__ void __launch_bounds__(256, 2)
gemm_proj(const uint32_t* __restrict__ Apk, const uint32_t* __restrict__ Bpk,
          const float* __restrict__ bias, float* __restrict__ Y)
{
    __shared__ uint32_t sm[3 * 4096];

    const int tid  = threadIdx.x;
    const int lane = tid & 31;
    const int w    = tid >> 5;
    const int wm   = w >> 2;
    const int wn   = w & 3;
    const int cq   = lane & 3;
    const int gq   = lane >> 2;

    const uint32_t smb = smem_u32(sm);
    const uint32_t* Ab = Apk + (size_t)blockIdx.y * (8 * 2048);
    const uint32_t* Bb = Bpk + (size_t)((blockIdx.z * NT + blockIdx.x) * 8) * 2048;

    float acc[4][4][4];
#pragma unroll
    for (int i = 0; i < 4; i++)
#pragma unroll
        for (int j = 0; j < 4; j++)
#pragma unroll
            for (int r = 0; r < 4; r++) acc[i][j][r] = 0.f;

#define P_ISSUE(c, buf) do {                                                      \
        uint32_t d_ = smb + (buf) * 16384;                                        \
        const uint32_t* A_ = Ab + (c) * 2048;                                     \
        const uint32_t* B_ = Bb + (c) * 2048;                                     \
        cpa16(d_ + tid * 32,             A_ + tid * 8);                           \
        cpa16(d_ + tid * 32 + 16,        A_ + tid * 8 + 4);                       \
        cpa16(d_ + 8192 + tid * 32,      B_ + tid * 8);                           \
        cpa16(d_ + 8192 + tid * 32 + 16, B_ + tid * 8 + 4);                       \
    } while (0)

    P_ISSUE(0, 0); CP_COMMIT();
    P_ISSUE(1, 1); CP_COMMIT();

#pragma unroll
    for (int c = 0; c < 8; c++) {
        if (c < 7) { CP_WAIT1(); } else { CP_WAIT0(); }
        __syncthreads();

        const int bo = (c % 3) * 4096;
#pragma unroll
        for (int kf = 0; kf < 2; kf++) {
            uint2 bh[4];
#pragma unroll
            for (int nf = 0; nf < 4; nf++)
                bh[nf] = *(const uint2*)&sm[bo + 2048 +
                            ((kf * 16 + wn * 4 + nf) * 32 + lane) * 2];
#pragma unroll
            for (int mf = 0; mf < 4; mf++) {
                uint4 hh = *(const uint4*)&sm[bo + (((wm * 4 + mf) * 2 + kf) * 32 + lane) * 4];
                uint32_t ah[4] = {hh.x, hh.y, hh.z, hh.w};
#pragma unroll
                for (int nf = 0; nf < 4; nf++)
                    MMAH(acc[mf][nf], ah, bh[nf].x, bh[nf].y);
            }
        }
        if (c < 6) { P_ISSUE(c + 2, (c + 2) % 3); CP_COMMIT(); }
    }
#undef P_ISSUE

    float* Yb = Y + (size_t)blockIdx.z * CC * HWN;
    const int m0 = blockIdx.y * 128;
    const int n0 = blockIdx.x * 128;
#pragma unroll
    for (int mf = 0; mf < 4; mf++) {
        int mA = m0 + wm * 64 + mf * 16 + gq;
        int mB = mA + 8;
        float bvA = bias[mA], bvB = bias[mB];
#pragma unroll
        for (int nf = 0; nf < 4; nf++) {
            int n = n0 + wn * 32 + nf * 8 + 2 * cq;
            *(float2*)&Yb[(size_t)mA * HWN + n] =
                make_float2(acc[mf][nf][0] + bvA, acc[mf][nf][1] + bvA);
            *(float2*)&Yb[(size_t)mB * HWN + n] =
                make_float2(acc[mf][nf][2] + bvB, acc[mf][nf][3] + bvB);
        }
    }
}

// ---------------------------------------------------------------------------
// Flash attention: QK 1-term fp16, PV 1-term fp16 (f32 acc); 3-stage
// cp.async pipeline, ONE sync per tile. smem: 3 x (K 4KB | V 4KB) = 24KB.
// ---------------------------------------------------------------------------
__global__ void __launch_bounds__(128)
attn_mma_h(const uint32_t* __restrict__ qpk,
           const uint32_t* __restrict__ kpk, const uint32_t* __restrict__ vpk,
           uint32_t* __restrict__ apk)
{
    __shared__ uint32_t smu[3 * 2048];

    const int tid  = threadIdx.x;
    const int lane = tid & 31;
    const int w    = tid >> 5;
    const int cq   = lane & 3;
    const int gq   = lane >> 2;

    const int bh = blockIdx.y;
    const int b  = bh >> 3, h = bh & 7;

    const uint32_t* qp = qpk + ((size_t)(bh * NT + blockIdx.x)) * 2048;
    const uint32_t* kt = kpk + (size_t)(bh * 36) * 1024;
    const uint32_t* vt = vpk + (size_t)(bh * 36) * 1024;
    const uint32_t smb = smem_u32(smu);

    uint32_t qa[2][2][4];
#pragma unroll
    for (int mf = 0; mf < 2; mf++)
#pragma unroll
        for (int kg = 0; kg < 2; kg++) {
            int rA = w * 32 + mf * 16 + gq, rB = rA + 8;
            int dp0 = kg * 8 + cq, dp2 = dp0 + 4;
            qa[mf][kg][0] = qp[dp0 * 128 + rA];
            qa[mf][kg][1] = qp[dp0 * 128 + rB];
            qa[mf][kg][2] = qp[dp2 * 128 + rA];
            qa[mf][kg][3] = qp[dp2 * 128 + rB];
        }

    float o[2][4][4];
#pragma unroll
    for (int mf = 0; mf < 2; mf++)
#pragma unroll
        for (int nf = 0; nf < 4; nf++)
#pragma unroll
            for (int i = 0; i < 4; i++) o[mf][nf][i] = 0.f;
    float rs[2][2] = {{0.f, 0.f}, {0.f, 0.f}};

#define A_ISSUE(t, buf) do {                                                      \
        uint32_t d_ = smb + (buf) * 8192;                                         \
        const uint32_t* K_ = kt + (t) * 1024;                                     \
        const uint32_t* V_ = vt + (t) * 1024;                                     \
        cpa16(d_ + tid * 32,             K_ + tid * 8);                           \
        cpa16(d_ + tid * 32 + 16,        K_ + tid * 8 + 4);                       \
        cpa16(d_ + 4096 + tid * 32,      V_ + tid * 8);                           \
        cpa16(d_ + 4096 + tid * 32 + 16, V_ + tid * 8 + 4);                       \
    } while (0)

    A_ISSUE(0, 0); CP_COMMIT();
    A_ISSUE(1, 1); CP_COMMIT();

    int buf = 0;
    for (int t = 0; t < 36; t++) {
        if (t < 35) { CP_WAIT1(); } else { CP_WAIT0(); }
        __syncthreads();

        const int bo = buf * 2048;
#pragma unroll
        for (int ch = 0; ch < 2; ch++) {
            float s[2][4][4];
#pragma unroll
            for (int mf = 0; mf < 2; mf++)
#pragma unroll
                for (int nf = 0; nf < 4; nf++)
#pragma unroll
                    for (int i = 0; i < 4; i++) s[mf][nf][i] = -CBIAS;

#pragma unroll
            for (int nf = 0; nf < 4; nf++) {
                uint2 kh[2];
#pragma unroll
                for (int kg = 0; kg < 2; kg++)
                    kh[kg] = *(const uint2*)&smu[bo + ((kg * 8 + ch * 4 + nf) * 32 + lane) * 2];
#pragma unroll
                for (int mf = 0; mf < 2; mf++)
#pragma unroll
                    for (int kg = 0; kg < 2; kg++)
                        MMAH(s[mf][nf], qa[mf][kg], kh[kg].x, kh[kg].y);
            }

#pragma unroll
            for (int mf = 0; mf < 2; mf++)
#pragma unroll
                for (int nf = 0; nf < 4; nf++)
#pragma unroll
                    for (int i = 0; i < 4; i++) {
                        float pv = ex2f(s[mf][nf][i]);
                        s[mf][nf][i] = pv;
                        rs[mf][i >> 1] += pv;
                    }

#pragma unroll
            for (int kg2 = 0; kg2 < 2; kg2++) {
                uint32_t pa[2][4];
#pragma unroll
                for (int mf = 0; mf < 2; mf++) {
                    pa[mf][0] = h2pack(s[mf][2 * kg2][0],     s[mf][2 * kg2][1]);
                    pa[mf][1] = h2pack(s[mf][2 * kg2][2],     s[mf][2 * kg2][3]);
                    pa[mf][2] = h2pack(s[mf][2 * kg2 + 1][0], s[mf][2 * kg2 + 1][1]);
                    pa[mf][3] = h2pack(s[mf][2 * kg2 + 1][2], s[mf][2 * kg2 + 1][3]);
                }
#pragma unroll
                for (int nf = 0; nf < 4; nf++) {
                    uint2 vv = *(const uint2*)&smu[bo + 1024 +
                                  (((ch * 2 + kg2) * 4 + nf) * 32 + lane) * 2];
#pragma unroll
                    for (int mf = 0; mf < 2; mf++)
                        MMAH(o[mf][nf], pa[mf], vv.x, vv.y);
                }
            }
        }
        if (t < 34) { A_ISSUE(t + 2, (buf + 2 >= 3) ? buf - 1 : buf + 2); CP_COMMIT(); }
        buf = (buf + 1 == 3) ? 0 : buf + 1;
    }
#undef A_ISSUE

#pragma unroll
    for (int mf = 0; mf < 2; mf++)
#pragma unroll
        for (int hf = 0; hf < 2; hf++) {
            float v = rs[mf][hf];
            v += __shfl_xor_sync(0xffffffffu, v, 1);
            v += __shfl_xor_sync(0xffffffffu, v, 2);
            rs[mf][hf] = 1.f / fmaxf(v, 1e-12f);
        }

    // epilogue: write proj's packed B (hi only)
    uint32_t* op = apk + (size_t)((b * NT + blockIdx.x) * 8 + h) * 2048;
#pragma unroll
    for (int mf = 0; mf < 2; mf++)
#pragma unroll
        for (int nfo = 0; nfo < 4; nfo++)
#pragma unroll
            for (int ih = 0; ih < 2; ih++) {
                float rv = rs[mf][ih];
                float f0 = o[mf][nfo][2 * ih + 0] * rv;
                float f1 = o[mf][nfo][2 * ih + 1] * rv;
                int k2  = nfo * 4 + cq;
                int kf  = k2 >> 3;
                int reg = (k2 & 7) >> 2;
                int nf  = w * 4 + mf * 2 + ih;
                op[((kf * 16 + nf) * 32 + lane) * 2 + reg] = h2pack(f0, f1);
            }
}

// ---------------------------------------------------------------------------
extern "C" void kernel_launch(void* const* d_in, const int* in_sizes, int n_in,
                              void* d_out, int out_size)
{
    const float* x      = (const float*)d_in[0];
    const float* w_qkv  = (const float*)d_in[1];
    const float* b_qkv  = (const float*)d_in[2];
    const float* w_proj = (const float*)d_in[3];
    const float* b_proj = (const float*)d_in[4];
    float*       out    = (float*)d_out;

    void *p_xpk, *p_wq, *p_wp, *p_qpk, *p_kpk, *p_vpk, *p_apk;
    cudaGetSymbolAddress(&p_xpk, g_xpk);
    cudaGetSymbolAddress(&p_wq,  g_wqkvpk);
    cudaGetSymbolAddress(&p_wp,  g_wprojpk);
    cudaGetSymbolAddress(&p_qpk, g_qpk);
    cudaGetSymbolAddress(&p_kpk, g_kpk);
    cudaGetSymbolAddress(&p_vpk, g_vpk);
    cudaGetSymbolAddress(&p_apk, g_apk);

    // 0) pack everything in one launch
    pack_all<<<1088, 256>>>(w_qkv, w_proj, x,
                            (uint32_t*)p_wq, (uint32_t*)p_wp, (uint32_t*)p_xpk);

    // 1) QKV projection (fp16 1-term, 3-stage pipeline) + fused Q/K/V packing
    {
        dim3 grid(NT, 6, BB);
        gemm_qkv<<<grid, 256>>>((const uint32_t*)p_wq, (const uint32_t*)p_xpk,
                                b_qkv, (uint32_t*)p_qpk, (uint32_t*)p_kpk,
                                (uint32_t*)p_vpk);
    }

    // 2) attention (3-stage pipeline, single sync per tile)
    {
        dim3 grid(NT, BB * HEADS);
        attn_mma_h<<<grid, 128>>>((const uint32_t*)p_qpk, (const uint32_t*)p_kpk,
                                  (const uint32_t*)p_vpk, (uint32_t*)p_apk);
    }

    // 3) output projection (fp16 1-term, 3-stage pipeline)
    {
        dim3 grid(NT, 2, BB);
        gemm_proj<<<grid, 256>>>((const uint32_t*)p_wp, (const uint32_t*)p_apk,
                                 b_proj, out);
    }
}